// round 5
// baseline (speedup 1.0000x reference)
#include <cuda_runtime.h>
#include <cstdint>
#include <cstddef>

// ---------------- problem constants ----------------
#define BS    8
#define NFEAT 64
#define NND   2048
#define JDIM  3
#define CH    128                  // 2*NOUT
#define KDIM  6144                 // NND*JDIM
#define ZN    (BS*CH*NND)          // 2097152 zbn elements
#define CHUNK 32                   // fp32 of K per chunk (128 B per row)
#define NCH   (KDIM/CHUNK)         // 192
#define STAGES 4
#define MT    64                   // m-rows per CTA tile
#define WTILEB (MT*CHUNK*4)        // 8192  W tile bytes
#define PTILEB (128*CHUNK*4)       // 16384 P tile bytes
#define STAGEB (WTILEB+PTILEB)     // 24576
#define DYN2  (STAGES*STAGEB)      // 98304
#define DYN1  65536

// ---------------- device scratch ----------------
__device__ float g_P[(size_t)BS*CH*KDIM];   // 25.2 MB
__device__ float g_z[(size_t)ZN];           // 8.4 MB
__device__ float g_S1[CH];
__device__ float g_S2[CH];
__device__ float g_misc[2];                 // total, M0
__device__ float g_scale[CH];
__device__ float g_shift[CH];

// ---------------- helpers ----------------
__device__ __forceinline__ uint32_t smem_u32(const void* p) {
    uint32_t a;
    asm("{ .reg .u64 t; cvta.to.shared.u64 t, %1; cvt.u32.u64 %0, t; }" : "=r"(a) : "l"(p));
    return a;
}
__device__ __forceinline__ void cp_async16(uint32_t dst, const void* src) {
    asm volatile("cp.async.cg.shared.global [%0], [%1], 16;" :: "r"(dst), "l"(src) : "memory");
}
#define CP_COMMIT() asm volatile("cp.async.commit_group;" ::: "memory")
#define CP_WAIT(n)  asm volatile("cp.async.wait_group %0;" :: "n"(n) : "memory")

__device__ __forceinline__ void mma_tf32(float* d, const uint32_t* a, const uint32_t* b) {
    asm volatile(
        "mma.sync.aligned.m16n8k8.row.col.f32.tf32.tf32.f32 "
        "{%0,%1,%2,%3}, {%4,%5,%6,%7}, {%8,%9}, {%0,%1,%2,%3};"
        : "+f"(d[0]), "+f"(d[1]), "+f"(d[2]), "+f"(d[3])
        : "r"(a[0]), "r"(a[1]), "r"(a[2]), "r"(a[3]), "r"(b[0]), "r"(b[1]));
}

// swizzled byte offset of float (row, k) in a [rows x 32] fp32 tile, 128B rows
__device__ __forceinline__ int swoff(int row, int k) {
    return row*128 + ((((k >> 2) ^ (row & 7))) << 4) + ((k & 3) << 2);
}
__device__ __forceinline__ int segoff(int row, int seg) {   // seg = 16B unit 0..7
    return row*128 + ((seg ^ (row & 7)) << 4);
}

// ---------------- K0: init reductions ----------------
__global__ void k0_init(const float* __restrict__ Nb, const float* __restrict__ mask) {
    int tid = threadIdx.x;
    if (tid < CH) { g_S1[tid] = 0.0f; g_S2[tid] = 0.0f; }
    float acc = 0.0f;
    for (int i = tid; i < BS*NND; i += 256) acc += mask[i];
    __shared__ float red[256];
    red[tid] = acc;
    __syncthreads();
    for (int s = 128; s > 0; s >>= 1) {
        if (tid < s) red[tid] += red[tid + s];
        __syncthreads();
    }
    if (tid == 0) {
        float tot = 0.0f;
        for (int i = 0; i < BS; i++) tot += Nb[i];
        g_misc[0] = tot;
        g_misc[1] = red[0];
    }
}

// ---------------- dummy kernel: keeps k2 in the ncu capture slot ----------------
__global__ void k_nop() {}

// ---------------- K1: P[b,o,n*3+j] = sum_f C[o, j*64+f] * X[b,f,n] ----------------
__global__ void __launch_bounds__(256, 1)
k1_gemm(const float* __restrict__ X, const float* __restrict__ cv1_w,
        const float* __restrict__ cv2_w) {
    extern __shared__ float sm1[];
    float* As = sm1;              // [64 f][128 o]
    float* Xs = sm1 + 64*128;     // [64 f][128 n]
    int tid = threadIdx.x;
    int nt = blockIdx.x, b = blockIdx.y, j = blockIdx.z;

    #pragma unroll
    for (int i = 0; i < 8; i++) {
        int q = i*256 + tid;
        int o  = q & 127;
        int f4 = q >> 7;
        const float* src = ((o < 64) ? (cv2_w + o*192) : (cv1_w + (o-64)*192)) + j*64 + f4*4;
        float4 v = *(const float4*)src;
        As[(f4*4+0)*128 + o] = v.x;
        As[(f4*4+1)*128 + o] = v.y;
        As[(f4*4+2)*128 + o] = v.z;
        As[(f4*4+3)*128 + o] = v.w;
    }
    #pragma unroll
    for (int i = 0; i < 8; i++) {
        int q = i*256 + tid;
        int n4 = q & 31;
        int f  = q >> 5;
        float4 v = __ldg((const float4*)(X + ((size_t)(b*NFEAT + f))*NND + nt*128 + n4*4));
        *(float4*)(Xs + f*128 + n4*4) = v;
    }
    __syncthreads();

    int tx = tid & 15, ty = tid >> 4;
    float acc[8][8];
    #pragma unroll
    for (int i = 0; i < 8; i++)
        #pragma unroll
        for (int u = 0; u < 8; u++) acc[i][u] = 0.0f;

    #pragma unroll 8
    for (int f = 0; f < 64; f++) {
        float a[8], bb[8];
        *(float4*)(a)    = *(const float4*)(As + f*128 + ty*8);
        *(float4*)(a+4)  = *(const float4*)(As + f*128 + ty*8 + 4);
        *(float4*)(bb)   = *(const float4*)(Xs + f*128 + tx*8);
        *(float4*)(bb+4) = *(const float4*)(Xs + f*128 + tx*8 + 4);
        #pragma unroll
        for (int i = 0; i < 8; i++)
            #pragma unroll
            for (int u = 0; u < 8; u++)
                acc[i][u] = fmaf(a[i], bb[u], acc[i][u]);
    }
    #pragma unroll
    for (int i = 0; i < 8; i++) {
        int o = ty*8 + i;
        float* dst = g_P + ((size_t)(b*CH + o))*KDIM + j;
        int n0 = nt*128 + tx*8;
        #pragma unroll
        for (int u = 0; u < 8; u++)
            dst[(size_t)(n0 + u)*3] = acc[i][u];
    }
}

// ---------------- K2: D = W * P^T via mma.sync tf32, fused W copy ----------------
// 256 CTAs (32 m-tiles of 64 rows x 8 batches), 256 thr, 2 CTAs/SM.
__device__ __forceinline__ void k2_load_stage(char* sm, const float* wsrc,
                                              const float* psrc, int c, int tid) {
    // W tile: 64 rows x 8 segs = 512 float4
    #pragma unroll
    for (int i = 0; i < 2; i++) {
        int q = i*256 + tid;
        int row = q >> 3, seg = q & 7;
        cp_async16(smem_u32(sm + segoff(row, seg)),
                   wsrc + (size_t)row*KDIM + c*CHUNK + seg*4);
    }
    // P tile: 128 rows x 8 segs = 1024 float4
    #pragma unroll
    for (int i = 0; i < 4; i++) {
        int q = i*256 + tid;
        int row = q >> 3, seg = q & 7;
        cp_async16(smem_u32(sm + WTILEB + segoff(row, seg)),
                   psrc + (size_t)row*KDIM + c*CHUNK + seg*4);
    }
}

__global__ void __launch_bounds__(256, 2)
k2_gemm(const float* __restrict__ W, const float* __restrict__ cv1_b,
        const float* __restrict__ cv2_b, float* __restrict__ outW) {
    extern __shared__ char dyn2[];
    __shared__ float s_bias[CH];

    int tid = threadIdx.x;
    int wid = tid >> 5, lane = tid & 31;
    int wy = wid >> 2, wx = wid & 3;       // 2x4 warp grid: wy m-group(32), wx o-group(32)
    int g = lane >> 2, tig = lane & 3;
    int mt = blockIdx.x, b = blockIdx.y;

    if (tid < CH) s_bias[tid] = (tid < 64) ? cv2_b[tid] : cv1_b[tid - 64];

    const float* wsrc = W    + ((size_t)(b*NND + mt*MT))*KDIM;
    float*       wdst = outW + ((size_t)(b*NND + mt*MT))*KDIM;
    const float* psrc = g_P  + ((size_t)(b*CH))*KDIM;

    float acc[2][4][4];
    #pragma unroll
    for (int t = 0; t < 2; t++)
        #pragma unroll
        for (int ot = 0; ot < 4; ot++)
            #pragma unroll
            for (int r = 0; r < 4; r++) acc[t][ot][r] = 0.0f;

    #pragma unroll
    for (int s = 0; s < STAGES; s++) {
        k2_load_stage(dyn2 + s*STAGEB, wsrc, psrc, s, tid);
        CP_COMMIT();
    }

    for (int c = 0; c < NCH; c++) {
        CP_WAIT(STAGES - 1);
        __syncthreads();
        char* sw = dyn2 + (c % STAGES)*STAGEB;
        char* sp = sw + WTILEB;

        // fused W copy-out: de-swizzle smem -> outW
        #pragma unroll
        for (int i = 0; i < 2; i++) {
            int q = i*256 + tid;
            int row = q >> 3, seg = q & 7;
            float4 v = *(const float4*)(sw + segoff(row, seg));
            *(float4*)(wdst + (size_t)row*KDIM + c*CHUNK + seg*4) = v;
        }

        // mma over 4 k-steps of 8
        #pragma unroll
        for (int ks = 0; ks < 4; ks++) {
            uint32_t a[2][4];
            uint32_t bf[4][2];
            int k0 = ks*8 + tig, k1 = k0 + 4;
            #pragma unroll
            for (int t = 0; t < 2; t++) {
                int r0 = wy*32 + t*16 + g, r1 = r0 + 8;
                a[t][0] = *(const uint32_t*)(sw + swoff(r0, k0));
                a[t][1] = *(const uint32_t*)(sw + swoff(r1, k0));
                a[t][2] = *(const uint32_t*)(sw + swoff(r0, k1));
                a[t][3] = *(const uint32_t*)(sw + swoff(r1, k1));
            }
            #pragma unroll
            for (int ot = 0; ot < 4; ot++) {
                int o = wx*32 + ot*8 + g;
                bf[ot][0] = *(const uint32_t*)(sp + swoff(o, k0));
                bf[ot][1] = *(const uint32_t*)(sp + swoff(o, k1));
            }
            #pragma unroll
            for (int t = 0; t < 2; t++)
                #pragma unroll
                for (int ot = 0; ot < 4; ot++)
                    mma_tf32(acc[t][ot], a[t], bf[ot]);
        }

        __syncthreads();
        if (c + STAGES < NCH)
            k2_load_stage(sw, wsrc, psrc, c + STAGES, tid);
        CP_COMMIT();
    }

    // epilogue: bias + relu -> g_z[b, o, mt*64 + m]
    #pragma unroll
    for (int t = 0; t < 2; t++) {
        int m0 = wy*32 + t*16 + g;
        #pragma unroll
        for (int ot = 0; ot < 4; ot++) {
            int o0 = wx*32 + ot*8 + 2*tig;
            float* z0 = g_z + ((size_t)(b*CH + o0))*NND + mt*MT;
            float* z1 = z0 + NND;   // o0+1
            float b0 = s_bias[o0], b1 = s_bias[o0+1];
            z0[m0]     = fmaxf(acc[t][ot][0] + b0, 0.0f);
            z1[m0]     = fmaxf(acc[t][ot][1] + b1, 0.0f);
            z0[m0 + 8] = fmaxf(acc[t][ot][2] + b0, 0.0f);
            z1[m0 + 8] = fmaxf(acc[t][ot][3] + b1, 0.0f);
        }
    }
}

// ---------------- K2b: per-channel masked sums ----------------
__global__ void __launch_bounds__(256, 4)
k2b_stats(const float* __restrict__ mask) {
    int row = blockIdx.x;           // b*128 + o
    int o = row & 127, b = row >> 7;
    const float* z = g_z + (size_t)row*NND;
    const float* mrow = mask + (size_t)b*NND;
    int tid = threadIdx.x;
    float s1 = 0.0f, s2 = 0.0f;
    for (int i = tid; i < NND/4; i += 256) {
        float4 v  = *(const float4*)(z + i*4);
        float4 mk = __ldg((const float4*)(mrow + i*4));
        s1 += v.x*mk.x + v.y*mk.y + v.z*mk.z + v.w*mk.w;
        s2 += v.x*v.x*mk.x + v.y*v.y*mk.y + v.z*v.z*mk.z + v.w*v.w*mk.w;
    }
    #pragma unroll
    for (int d = 16; d > 0; d >>= 1) {
        s1 += __shfl_xor_sync(0xFFFFFFFFu, s1, d);
        s2 += __shfl_xor_sync(0xFFFFFFFFu, s2, d);
    }
    __shared__ float r1[8], r2[8];
    if ((tid & 31) == 0) { r1[tid >> 5] = s1; r2[tid >> 5] = s2; }
    __syncthreads();
    if (tid == 0) {
        float t1 = 0.0f, t2 = 0.0f;
        #pragma unroll
        for (int i = 0; i < 8; i++) { t1 += r1[i]; t2 += r2[i]; }
        atomicAdd(&g_S1[o], t1);
        atomicAdd(&g_S2[o], t2);
    }
}

// ---------------- K2c: finalize scale/shift ----------------
__global__ void k2c_finstats(const float* __restrict__ gamma, const float* __restrict__ beta) {
    int o = threadIdx.x;
    if (o >= CH) return;
    float total = g_misc[0], M0 = g_misc[1];
    float s1 = g_S1[o], s2 = g_S2[o];
    float mean = s1 / total;
    float var = (s2 - 2.0f*mean*s1 + mean*mean*M0) / total;
    float sc = gamma[o] * rsqrtf(var + 1e-5f);
    g_scale[o] = sc;
    g_shift[o] = beta[o] - mean*sc;
}

// ---------------- K3: apply BN affine + mask -> out ----------------
__global__ void __launch_bounds__(256, 8)
k3_apply(const float* __restrict__ mask, float* __restrict__ out) {
    int idx4 = blockIdx.x*256 + threadIdx.x;   // float4 index
    int row = idx4 >> 9;                       // b*128 + o
    int o = row & 127, b = row >> 7;
    int m4 = idx4 & 511;
    float4 z  = *(const float4*)(g_z + (size_t)row*NND + m4*4);
    float4 mk = __ldg((const float4*)(mask + (size_t)b*NND + m4*4));
    float sc = g_scale[o], sh = g_shift[o];
    float4 r;
    r.x = (z.x*sc + sh)*mk.x;
    r.y = (z.y*sc + sh)*mk.y;
    r.z = (z.z*sc + sh)*mk.z;
    r.w = (z.w*sc + sh)*mk.w;
    *(float4*)(out + (size_t)row*NND + m4*4) = r;
}

// ---------------- launch ----------------
extern "C" void kernel_launch(void* const* d_in, const int* in_sizes, int n_in,
                              void* d_out, int out_size) {
    (void)in_sizes; (void)n_in; (void)out_size;
    const float* X     = (const float*)d_in[0];
    const float* W     = (const float*)d_in[1];
    const float* Nb    = (const float*)d_in[2];
    const float* mask  = (const float*)d_in[3];
    const float* cv1_w = (const float*)d_in[4];
    const float* cv1_b = (const float*)d_in[5];
    const float* cv2_w = (const float*)d_in[6];
    const float* cv2_b = (const float*)d_in[7];
    const float* gamma = (const float*)d_in[8];
    const float* beta  = (const float*)d_in[9];
    float* out  = (float*)d_out;
    float* outW = out + ZN;

    cudaFuncSetAttribute(k1_gemm, cudaFuncAttributeMaxDynamicSharedMemorySize, DYN1);
    cudaFuncSetAttribute(k2_gemm, cudaFuncAttributeMaxDynamicSharedMemorySize, DYN2);

    k0_init<<<1, 256>>>(Nb, mask);                              // launch 0
    k1_gemm<<<dim3(16, 8, 3), 256, DYN1>>>(X, cv1_w, cv2_w);    // launch 1
    k_nop<<<1, 32>>>();                                         // launch 2 (slot shim)
    k2_gemm<<<dim3(32, 8), 256, DYN2>>>(W, cv1_b, cv2_b, outW); // launch 3 <- ncu slot
    k2b_stats<<<BS*CH, 256>>>(mask);
    k2c_finstats<<<1, 128>>>(gamma, beta);
    k3_apply<<<ZN/4/256, 256>>>(mask, out);
}

// round 6
// speedup vs baseline: 1.0578x; 1.0578x over previous
#include <cuda_runtime.h>
#include <cstdint>
#include <cstddef>

// ---------------- problem constants ----------------
#define BS    8
#define NFEAT 64
#define NND   2048
#define JDIM  3
#define CH    128                  // 2*NOUT
#define KDIM  6144                 // NND*JDIM
#define ZN    (BS*CH*NND)          // 2097152 zbn elements
#define CHUNK 32                   // fp32 of K per chunk (128 B per row)
#define NCH   (KDIM/CHUNK)         // 192
#define STAGES 5
#define LOOKAHEAD 4
#define MT    128                  // m-rows per CTA tile
#define WTILEB (MT*CHUNK*4)        // 16384 W tile bytes
#define PTILEB (128*CHUNK*4)       // 16384 P tile bytes
#define STAGEB (WTILEB+PTILEB)     // 32768
#define DYN2  (STAGES*STAGEB)      // 163840
#define DYN1  65536
#define THR2  512

// ---------------- device scratch ----------------
__device__ float g_P[(size_t)BS*CH*KDIM];   // 25.2 MB
__device__ float g_z[(size_t)ZN];           // 8.4 MB
__device__ float g_S1[CH];
__device__ float g_S2[CH];
__device__ float g_misc[2];                 // total, M0
__device__ float g_scale[CH];
__device__ float g_shift[CH];

// ---------------- helpers ----------------
__device__ __forceinline__ uint32_t smem_u32(const void* p) {
    uint32_t a;
    asm("{ .reg .u64 t; cvta.to.shared.u64 t, %1; cvt.u32.u64 %0, t; }" : "=r"(a) : "l"(p));
    return a;
}
__device__ __forceinline__ void cp_async16(uint32_t dst, const void* src) {
    asm volatile("cp.async.cg.shared.global [%0], [%1], 16;" :: "r"(dst), "l"(src) : "memory");
}
#define CP_COMMIT() asm volatile("cp.async.commit_group;" ::: "memory")
#define CP_WAIT(n)  asm volatile("cp.async.wait_group %0;" :: "n"(n) : "memory")

__device__ __forceinline__ void mma_tf32(float* d, const uint32_t* a, const uint32_t* b) {
    asm volatile(
        "mma.sync.aligned.m16n8k8.row.col.f32.tf32.tf32.f32 "
        "{%0,%1,%2,%3}, {%4,%5,%6,%7}, {%8,%9}, {%0,%1,%2,%3};"
        : "+f"(d[0]), "+f"(d[1]), "+f"(d[2]), "+f"(d[3])
        : "r"(a[0]), "r"(a[1]), "r"(a[2]), "r"(a[3]), "r"(b[0]), "r"(b[1]));
}
__device__ __forceinline__ void ldmx4(uint32_t* r, uint32_t addr) {
    asm volatile(
        "ldmatrix.sync.aligned.m8n8.x4.shared.b16 {%0,%1,%2,%3}, [%4];"
        : "=r"(r[0]), "=r"(r[1]), "=r"(r[2]), "=r"(r[3]) : "r"(addr));
}

// swizzled byte offset helpers for a [rows x 32] fp32 tile, 128B rows
__device__ __forceinline__ int segoff(int row, int seg) {   // seg = 16B unit 0..7
    return row*128 + ((seg ^ (row & 7)) << 4);
}

// ---------------- K0: init reductions ----------------
__global__ void k0_init(const float* __restrict__ Nb, const float* __restrict__ mask) {
    int tid = threadIdx.x;
    if (tid < CH) { g_S1[tid] = 0.0f; g_S2[tid] = 0.0f; }
    float acc = 0.0f;
    for (int i = tid; i < BS*NND; i += 256) acc += mask[i];
    __shared__ float red[256];
    red[tid] = acc;
    __syncthreads();
    for (int s = 128; s > 0; s >>= 1) {
        if (tid < s) red[tid] += red[tid + s];
        __syncthreads();
    }
    if (tid == 0) {
        float tot = 0.0f;
        for (int i = 0; i < BS; i++) tot += Nb[i];
        g_misc[0] = tot;
        g_misc[1] = red[0];
    }
}

// ---------------- dummy kernel: keeps k2 in the ncu capture slot ----------------
__global__ void k_nop() {}

// ---------------- K1: P[b,o,n*3+j] = sum_f C[o, j*64+f] * X[b,f,n] ----------------
__global__ void __launch_bounds__(256, 1)
k1_gemm(const float* __restrict__ X, const float* __restrict__ cv1_w,
        const float* __restrict__ cv2_w) {
    extern __shared__ float sm1[];
    float* As = sm1;              // [64 f][128 o]
    float* Xs = sm1 + 64*128;     // [64 f][128 n]
    int tid = threadIdx.x;
    int nt = blockIdx.x, b = blockIdx.y, j = blockIdx.z;

    #pragma unroll
    for (int i = 0; i < 8; i++) {
        int q = i*256 + tid;
        int o  = q & 127;
        int f4 = q >> 7;
        const float* src = ((o < 64) ? (cv2_w + o*192) : (cv1_w + (o-64)*192)) + j*64 + f4*4;
        float4 v = *(const float4*)src;
        As[(f4*4+0)*128 + o] = v.x;
        As[(f4*4+1)*128 + o] = v.y;
        As[(f4*4+2)*128 + o] = v.z;
        As[(f4*4+3)*128 + o] = v.w;
    }
    #pragma unroll
    for (int i = 0; i < 8; i++) {
        int q = i*256 + tid;
        int n4 = q & 31;
        int f  = q >> 5;
        float4 v = __ldg((const float4*)(X + ((size_t)(b*NFEAT + f))*NND + nt*128 + n4*4));
        *(float4*)(Xs + f*128 + n4*4) = v;
    }
    __syncthreads();

    int tx = tid & 15, ty = tid >> 4;
    float acc[8][8];
    #pragma unroll
    for (int i = 0; i < 8; i++)
        #pragma unroll
        for (int u = 0; u < 8; u++) acc[i][u] = 0.0f;

    #pragma unroll 8
    for (int f = 0; f < 64; f++) {
        float a[8], bb[8];
        *(float4*)(a)    = *(const float4*)(As + f*128 + ty*8);
        *(float4*)(a+4)  = *(const float4*)(As + f*128 + ty*8 + 4);
        *(float4*)(bb)   = *(const float4*)(Xs + f*128 + tx*8);
        *(float4*)(bb+4) = *(const float4*)(Xs + f*128 + tx*8 + 4);
        #pragma unroll
        for (int i = 0; i < 8; i++)
            #pragma unroll
            for (int u = 0; u < 8; u++)
                acc[i][u] = fmaf(a[i], bb[u], acc[i][u]);
    }
    #pragma unroll
    for (int i = 0; i < 8; i++) {
        int o = ty*8 + i;
        float* dst = g_P + ((size_t)(b*CH + o))*KDIM + j;
        int n0 = nt*128 + tx*8;
        #pragma unroll
        for (int u = 0; u < 8; u++)
            dst[(size_t)(n0 + u)*3] = acc[i][u];
    }
}

// ---------------- K2: D = W * P^T via mma.sync tf32 + ldmatrix, fused W copy ----------------
__device__ __forceinline__ void k2_load_stage(char* sm, const float* wsrc,
                                              const float* psrc, int c, int tid) {
    // W tile: 128 rows x 8 segs = 1024 float4 (512 thr -> 2 each)
    #pragma unroll
    for (int i = 0; i < 2; i++) {
        int q = i*THR2 + tid;
        int row = q >> 3, seg = q & 7;
        cp_async16(smem_u32(sm + segoff(row, seg)),
                   wsrc + (size_t)row*KDIM + c*CHUNK + seg*4);
    }
    // P tile: 128 rows x 8 segs = 1024 float4
    #pragma unroll
    for (int i = 0; i < 2; i++) {
        int q = i*THR2 + tid;
        int row = q >> 3, seg = q & 7;
        cp_async16(smem_u32(sm + WTILEB + segoff(row, seg)),
                   psrc + (size_t)row*KDIM + c*CHUNK + seg*4);
    }
}

__global__ void __launch_bounds__(THR2, 1)
k2_gemm(const float* __restrict__ W, const float* __restrict__ cv1_b,
        const float* __restrict__ cv2_b, float* __restrict__ outW) {
    extern __shared__ char dyn2[];
    __shared__ float s_bias[CH];

    int tid = threadIdx.x;
    int wid = tid >> 5, lane = tid & 31;
    int wy = wid >> 2, wx = wid & 3;       // 4x4 warp grid: wy m-group(32), wx o-group(32)
    int g = lane >> 2, tig = lane & 3;
    int mt = blockIdx.x, b = blockIdx.y;

    if (tid < CH) s_bias[tid] = (tid < 64) ? cv2_b[tid] : cv1_b[tid - 64];

    const float* wsrc = W    + ((size_t)(b*NND + mt*MT))*KDIM;
    float*       wdst = outW + ((size_t)(b*NND + mt*MT))*KDIM;
    const float* psrc = g_P  + ((size_t)(b*CH))*KDIM;

    uint32_t dyn_u = smem_u32(dyn2);

    // ldmatrix address offsets (within-tile, swizzled), per x4 instruction.
    // A (W tile): matrix m = lane>>3: rows base + (m&1)*8, k-block (m>>1)
    int mIdx = lane >> 3;
    uint32_t offA[2];
    #pragma unroll
    for (int t = 0; t < 2; t++) {
        int rA = wy*32 + t*16 + (mIdx & 1)*8 + (lane & 7);
        offA[t] = (uint32_t)(rA*128 + ((((mIdx >> 1) ^ (rA & 7))) << 4));
    }
    // B (P tile): x4 group h: matrix m: ot = h*2 + (m>>1), k-block (m&1)
    uint32_t offB[2];
    #pragma unroll
    for (int h = 0; h < 2; h++) {
        int ot = h*2 + (mIdx >> 1);
        int rB = wx*32 + ot*8 + (lane & 7);
        offB[h] = (uint32_t)(rB*128 + ((((mIdx & 1) ^ (rB & 7))) << 4));
    }

    float acc[2][4][4];
    #pragma unroll
    for (int t = 0; t < 2; t++)
        #pragma unroll
        for (int ot = 0; ot < 4; ot++)
            #pragma unroll
            for (int r = 0; r < 4; r++) acc[t][ot][r] = 0.0f;

    // prologue: prefetch LOOKAHEAD chunks
    #pragma unroll
    for (int s = 0; s < LOOKAHEAD; s++) {
        k2_load_stage(dyn2 + s*STAGEB, wsrc, psrc, s, tid);
        CP_COMMIT();
    }

    for (int c = 0; c < NCH; c++) {
        CP_WAIT(LOOKAHEAD - 1);
        __syncthreads();                      // chunk c ready; all warps done with c-1

        // issue next loads first (into the buffer consumed at iter c-1)
        if (c + LOOKAHEAD < NCH)
            k2_load_stage(dyn2 + ((c + LOOKAHEAD) % STAGES)*STAGEB, wsrc, psrc,
                          c + LOOKAHEAD, tid);
        CP_COMMIT();

        uint32_t swu = dyn_u + (uint32_t)((c % STAGES)*STAGEB);
        uint32_t spu = swu + WTILEB;
        char*    sw  = dyn2 + (c % STAGES)*STAGEB;

        // mma over 4 k-steps of 8, fragments via ldmatrix
        #pragma unroll
        for (int ks = 0; ks < 4; ks++) {
            uint32_t xo = (uint32_t)(ks << 5);
            uint32_t a[2][4];
            uint32_t bq[4][2];
            ldmx4(a[0], swu + (offA[0] ^ xo));
            ldmx4(a[1], swu + (offA[1] ^ xo));
            {
                uint32_t r[4];
                ldmx4(r, spu + (offB[0] ^ xo));
                bq[0][0] = r[0]; bq[0][1] = r[1]; bq[1][0] = r[2]; bq[1][1] = r[3];
                ldmx4(r, spu + (offB[1] ^ xo));
                bq[2][0] = r[0]; bq[2][1] = r[1]; bq[3][0] = r[2]; bq[3][1] = r[3];
            }
            #pragma unroll
            for (int t = 0; t < 2; t++)
                #pragma unroll
                for (int ot = 0; ot < 4; ot++)
                    mma_tf32(acc[t][ot], a[t], bq[ot]);
        }

        // fused W copy-out: de-swizzle smem -> outW
        #pragma unroll
        for (int i = 0; i < 2; i++) {
            int q = i*THR2 + tid;
            int row = q >> 3, seg = q & 7;
            float4 v = *(const float4*)(sw + segoff(row, seg));
            *(float4*)(wdst + (size_t)row*KDIM + c*CHUNK + seg*4) = v;
        }
    }

    // epilogue: bias + relu -> g_z[b, o, mt*128 + m]
    #pragma unroll
    for (int t = 0; t < 2; t++) {
        int m0 = wy*32 + t*16 + g;
        #pragma unroll
        for (int ot = 0; ot < 4; ot++) {
            int o0 = wx*32 + ot*8 + 2*tig;
            float* z0 = g_z + ((size_t)(b*CH + o0))*NND + mt*MT;
            float* z1 = z0 + NND;   // o0+1
            float b0 = s_bias[o0], b1 = s_bias[o0+1];
            z0[m0]     = fmaxf(acc[t][ot][0] + b0, 0.0f);
            z1[m0]     = fmaxf(acc[t][ot][1] + b1, 0.0f);
            z0[m0 + 8] = fmaxf(acc[t][ot][2] + b0, 0.0f);
            z1[m0 + 8] = fmaxf(acc[t][ot][3] + b1, 0.0f);
        }
    }
}

// ---------------- K2b: per-channel masked sums ----------------
__global__ void __launch_bounds__(256, 4)
k2b_stats(const float* __restrict__ mask) {
    int row = blockIdx.x;           // b*128 + o
    int o = row & 127, b = row >> 7;
    const float* z = g_z + (size_t)row*NND;
    const float* mrow = mask + (size_t)b*NND;
    int tid = threadIdx.x;
    float s1 = 0.0f, s2 = 0.0f;
    for (int i = tid; i < NND/4; i += 256) {
        float4 v  = *(const float4*)(z + i*4);
        float4 mk = __ldg((const float4*)(mrow + i*4));
        s1 += v.x*mk.x + v.y*mk.y + v.z*mk.z + v.w*mk.w;
        s2 += v.x*v.x*mk.x + v.y*v.y*mk.y + v.z*v.z*mk.z + v.w*v.w*mk.w;
    }
    #pragma unroll
    for (int d = 16; d > 0; d >>= 1) {
        s1 += __shfl_xor_sync(0xFFFFFFFFu, s1, d);
        s2 += __shfl_xor_sync(0xFFFFFFFFu, s2, d);
    }
    __shared__ float r1[8], r2[8];
    if ((tid & 31) == 0) { r1[tid >> 5] = s1; r2[tid >> 5] = s2; }
    __syncthreads();
    if (tid == 0) {
        float t1 = 0.0f, t2 = 0.0f;
        #pragma unroll
        for (int i = 0; i < 8; i++) { t1 += r1[i]; t2 += r2[i]; }
        atomicAdd(&g_S1[o], t1);
        atomicAdd(&g_S2[o], t2);
    }
}

// ---------------- K2c: finalize scale/shift ----------------
__global__ void k2c_finstats(const float* __restrict__ gamma, const float* __restrict__ beta) {
    int o = threadIdx.x;
    if (o >= CH) return;
    float total = g_misc[0], M0 = g_misc[1];
    float s1 = g_S1[o], s2 = g_S2[o];
    float mean = s1 / total;
    float var = (s2 - 2.0f*mean*s1 + mean*mean*M0) / total;
    float sc = gamma[o] * rsqrtf(var + 1e-5f);
    g_scale[o] = sc;
    g_shift[o] = beta[o] - mean*sc;
}

// ---------------- K3: apply BN affine + mask -> out ----------------
__global__ void __launch_bounds__(256, 8)
k3_apply(const float* __restrict__ mask, float* __restrict__ out) {
    int idx4 = blockIdx.x*256 + threadIdx.x;   // float4 index
    int row = idx4 >> 9;                       // b*128 + o
    int o = row & 127, b = row >> 7;
    int m4 = idx4 & 511;
    float4 z  = *(const float4*)(g_z + (size_t)row*NND + m4*4);
    float4 mk = __ldg((const float4*)(mask + (size_t)b*NND + m4*4));
    float sc = g_scale[o], sh = g_shift[o];
    float4 r;
    r.x = (z.x*sc + sh)*mk.x;
    r.y = (z.y*sc + sh)*mk.y;
    r.z = (z.z*sc + sh)*mk.z;
    r.w = (z.w*sc + sh)*mk.w;
    *(float4*)(out + (size_t)row*NND + m4*4) = r;
}

// ---------------- launch ----------------
extern "C" void kernel_launch(void* const* d_in, const int* in_sizes, int n_in,
                              void* d_out, int out_size) {
    (void)in_sizes; (void)n_in; (void)out_size;
    const float* X     = (const float*)d_in[0];
    const float* W     = (const float*)d_in[1];
    const float* Nb    = (const float*)d_in[2];
    const float* mask  = (const float*)d_in[3];
    const float* cv1_w = (const float*)d_in[4];
    const float* cv1_b = (const float*)d_in[5];
    const float* cv2_w = (const float*)d_in[6];
    const float* cv2_b = (const float*)d_in[7];
    const float* gamma = (const float*)d_in[8];
    const float* beta  = (const float*)d_in[9];
    float* out  = (float*)d_out;
    float* outW = out + ZN;

    cudaFuncSetAttribute(k1_gemm, cudaFuncAttributeMaxDynamicSharedMemorySize, DYN1);
    cudaFuncSetAttribute(k2_gemm, cudaFuncAttributeMaxDynamicSharedMemorySize, DYN2);

    k0_init<<<1, 256>>>(Nb, mask);                               // launch 0
    k1_gemm<<<dim3(16, 8, 3), 256, DYN1>>>(X, cv1_w, cv2_w);     // launch 1
    k_nop<<<1, 32>>>();                                          // launch 2 (slot shim)
    k2_gemm<<<dim3(16, 8), THR2, DYN2>>>(W, cv1_b, cv2_b, outW); // launch 3 <- ncu slot
    k2b_stats<<<BS*CH, 256>>>(mask);
    k2c_finstats<<<1, 128>>>(gamma, beta);
    k3_apply<<<ZN/4/256, 256>>>(mask, out);
}

// round 7
// speedup vs baseline: 1.1904x; 1.1254x over previous
#include <cuda_runtime.h>
#include <cstdint>
#include <cstddef>

// ---------------- problem constants ----------------
#define BS    8
#define NFEAT 64
#define NND   2048
#define JDIM  3
#define CH    128                  // 2*NOUT
#define KDIM  6144                 // NND*JDIM
#define ZN    (BS*CH*NND)          // 2097152 zbn elements
#define CHUNK 32                   // fp32 of K per chunk (128 B per row)
#define NCH   (KDIM/CHUNK)         // 192
#define STAGES 5
#define LOOKAHEAD 4
#define MT    128                  // m-rows per CTA tile
#define WTILEB (MT*CHUNK*4)        // 16384 W tile bytes
#define PTILEB (128*CHUNK*4)       // 16384 P tile bytes
#define STAGEB (WTILEB+PTILEB)     // 32768
#define DYN2  (STAGES*STAGEB)      // 163840
#define THR2  128                  // 4 warps, 2x2 grid of 64x64 tiles
#define DYN1  147456               // k1: As 32KB + Xs 16KB + stage 96KB

// ---------------- device scratch ----------------
__device__ float g_P[(size_t)BS*CH*KDIM];   // 25.2 MB
__device__ float g_z[(size_t)ZN];           // 8.4 MB
__device__ float g_S1[CH];
__device__ float g_S2[CH];
__device__ float g_misc[2];                 // total, M0
__device__ float g_scale[CH];
__device__ float g_shift[CH];

// ---------------- helpers ----------------
__device__ __forceinline__ uint32_t smem_u32(const void* p) {
    uint32_t a;
    asm("{ .reg .u64 t; cvta.to.shared.u64 t, %1; cvt.u32.u64 %0, t; }" : "=r"(a) : "l"(p));
    return a;
}
__device__ __forceinline__ void cp_async16(uint32_t dst, const void* src) {
    asm volatile("cp.async.cg.shared.global [%0], [%1], 16;" :: "r"(dst), "l"(src) : "memory");
}
#define CP_COMMIT() asm volatile("cp.async.commit_group;" ::: "memory")
#define CP_WAIT(n)  asm volatile("cp.async.wait_group %0;" :: "n"(n) : "memory")

__device__ __forceinline__ void mma_tf32(float* d, const uint32_t* a, const uint32_t* b) {
    asm volatile(
        "mma.sync.aligned.m16n8k8.row.col.f32.tf32.tf32.f32 "
        "{%0,%1,%2,%3}, {%4,%5,%6,%7}, {%8,%9}, {%0,%1,%2,%3};"
        : "+f"(d[0]), "+f"(d[1]), "+f"(d[2]), "+f"(d[3])
        : "r"(a[0]), "r"(a[1]), "r"(a[2]), "r"(a[3]), "r"(b[0]), "r"(b[1]));
}
__device__ __forceinline__ void ldmx4(uint32_t* r, uint32_t addr) {
    asm volatile(
        "ldmatrix.sync.aligned.m8n8.x4.shared.b16 {%0,%1,%2,%3}, [%4];"
        : "=r"(r[0]), "=r"(r[1]), "=r"(r[2]), "=r"(r[3]) : "r"(addr));
}
__device__ __forceinline__ int segoff(int row, int seg) {   // seg = 16B unit 0..7
    return row*128 + ((seg ^ (row & 7)) << 4);
}

// ---------------- K0: init reductions ----------------
__global__ void k0_init(const float* __restrict__ Nb, const float* __restrict__ mask) {
    int tid = threadIdx.x;
    if (tid < CH) { g_S1[tid] = 0.0f; g_S2[tid] = 0.0f; }
    float acc = 0.0f;
    for (int i = tid; i < BS*NND; i += 256) acc += mask[i];
    __shared__ float red[256];
    red[tid] = acc;
    __syncthreads();
    for (int s = 128; s > 0; s >>= 1) {
        if (tid < s) red[tid] += red[tid + s];
        __syncthreads();
    }
    if (tid == 0) {
        float tot = 0.0f;
        for (int i = 0; i < BS; i++) tot += Nb[i];
        g_misc[0] = tot;
        g_misc[1] = red[0];
    }
}

// ---------------- dummy kernel: keeps k2 in the ncu capture slot ----------------
__global__ void k_nop() {}

// ---------------- K1: P[b,o,n*3+j] = sum_f C[o, j*64+f] * X[b,f,n] ----------------
// One CTA covers all 3 j for a 64-node block: 3 compute passes stage into smem,
// then one fully-coalesced float4 write sweep of the interleaved k' layout.
__global__ void __launch_bounds__(256, 1)
k1_gemm(const float* __restrict__ X, const float* __restrict__ cv1_w,
        const float* __restrict__ cv2_w) {
    extern __shared__ float sm1[];
    float* As    = sm1;            // [64 f][128 o]      8192 floats
    float* Xs    = sm1 + 8192;     // [64 f][64 n]       4096 floats
    float* stage = sm1 + 12288;    // [128 o][192 k']    24576 floats
    int tid = threadIdx.x;
    int nt = blockIdx.x, b = blockIdx.y;

    // load X tile once: [64 f][64 n]
    #pragma unroll
    for (int i = 0; i < 4; i++) {
        int q = i*256 + tid;       // 0..1023 float4s
        int n4 = q & 15;           // 16 float4 per f-row
        int f  = q >> 4;
        float4 v = __ldg((const float4*)(X + ((size_t)(b*NFEAT + f))*NND + nt*64 + n4*4));
        *(float4*)(Xs + f*64 + n4*4) = v;
    }

    int tx = tid & 15, ty = tid >> 4;   // tx: 4-n group, ty: 8-o group

    for (int j = 0; j < JDIM; j++) {
        __syncthreads();
        // load C slice for this j: As[f][o]
        #pragma unroll
        for (int i = 0; i < 8; i++) {
            int q = i*256 + tid;          // 0..2047
            int o  = q & 127;
            int f4 = q >> 7;              // 0..15
            const float* src = ((o < 64) ? (cv2_w + o*192) : (cv1_w + (o-64)*192)) + j*64 + f4*4;
            float4 v = __ldg((const float4*)src);
            As[(f4*4+0)*128 + o] = v.x;
            As[(f4*4+1)*128 + o] = v.y;
            As[(f4*4+2)*128 + o] = v.z;
            As[(f4*4+3)*128 + o] = v.w;
        }
        __syncthreads();

        float acc[8][4];
        #pragma unroll
        for (int i = 0; i < 8; i++)
            #pragma unroll
            for (int u = 0; u < 4; u++) acc[i][u] = 0.0f;

        #pragma unroll 8
        for (int f = 0; f < 64; f++) {
            float a[8], bb[4];
            *(float4*)(a)   = *(const float4*)(As + f*128 + ty*8);
            *(float4*)(a+4) = *(const float4*)(As + f*128 + ty*8 + 4);
            *(float4*)(bb)  = *(const float4*)(Xs + f*64 + tx*4);
            #pragma unroll
            for (int i = 0; i < 8; i++)
                #pragma unroll
                for (int u = 0; u < 4; u++)
                    acc[i][u] = fmaf(a[i], bb[u], acc[i][u]);
        }
        // stage into interleaved k' layout
        #pragma unroll
        for (int i = 0; i < 8; i++) {
            int o = ty*8 + i;
            #pragma unroll
            for (int u = 0; u < 4; u++)
                stage[o*192 + (tx*4 + u)*3 + j] = acc[i][u];
        }
    }
    __syncthreads();

    // coalesced write-out: 128 rows x 48 float4
    #pragma unroll
    for (int i = 0; i < 24; i++) {
        int q = i*256 + tid;              // 0..6143
        int row = q / 48, c4 = q % 48;
        float4 v = *(const float4*)(stage + row*192 + c4*4);
        *(float4*)(g_P + ((size_t)(b*CH + row))*KDIM + nt*192 + c4*4) = v;
    }
}

// ---------------- K2: D = W * P^T, mma.sync tf32, 64x64 warp tiles, fused W copy ----------------
__device__ __forceinline__ void k2_load_stage(char* sm, const float* wsrc,
                                              const float* psrc, int c, int tid) {
    #pragma unroll
    for (int i = 0; i < 8; i++) {
        int q = i*THR2 + tid;
        int row = q >> 3, seg = q & 7;
        cp_async16(smem_u32(sm + segoff(row, seg)),
                   wsrc + (size_t)row*KDIM + c*CHUNK + seg*4);
    }
    #pragma unroll
    for (int i = 0; i < 8; i++) {
        int q = i*THR2 + tid;
        int row = q >> 3, seg = q & 7;
        cp_async16(smem_u32(sm + WTILEB + segoff(row, seg)),
                   psrc + (size_t)row*KDIM + c*CHUNK + seg*4);
    }
}

__global__ void __launch_bounds__(THR2, 1)
k2_gemm(const float* __restrict__ W, const float* __restrict__ cv1_b,
        const float* __restrict__ cv2_b, float* __restrict__ outW) {
    extern __shared__ char dyn2[];
    __shared__ float s_bias[CH];

    int tid = threadIdx.x;
    int wid = tid >> 5, lane = tid & 31;
    int wy = wid >> 1, wx = wid & 1;       // 2x2 warp grid, 64x64 tiles
    int g = lane >> 2, tig = lane & 3;
    int mt = blockIdx.x, b = blockIdx.y;

    if (tid < CH) s_bias[tid] = (tid < 64) ? cv2_b[tid] : cv1_b[tid - 64];

    const float* wsrc = W    + ((size_t)(b*NND + mt*MT))*KDIM;
    float*       wdst = outW + ((size_t)(b*NND + mt*MT))*KDIM;
    const float* psrc = g_P  + ((size_t)(b*CH))*KDIM;

    uint32_t dyn_u = smem_u32(dyn2);

    // ldmatrix offsets. mIdx = lane>>3 selects (row-half, k-half) / (o, k-half).
    int mIdx = lane >> 3;
    uint32_t offA[4];
    #pragma unroll
    for (int mg = 0; mg < 4; mg++) {
        int rA = wy*64 + mg*16 + (mIdx & 1)*8 + (lane & 7);
        offA[mg] = (uint32_t)(rA*128 + ((((mIdx >> 1) ^ (rA & 7))) << 4));
    }
    uint32_t offB[4];
    #pragma unroll
    for (int h = 0; h < 4; h++) {
        int ot = h*2 + (mIdx >> 1);
        int rB = wx*64 + ot*8 + (lane & 7);
        offB[h] = (uint32_t)(rB*128 + ((((mIdx & 1) ^ (rB & 7))) << 4));
    }

    float acc[4][8][4];
    #pragma unroll
    for (int t = 0; t < 4; t++)
        #pragma unroll
        for (int ot = 0; ot < 8; ot++)
            #pragma unroll
            for (int r = 0; r < 4; r++) acc[t][ot][r] = 0.0f;

    #pragma unroll
    for (int s = 0; s < LOOKAHEAD; s++) {
        k2_load_stage(dyn2 + s*STAGEB, wsrc, psrc, s, tid);
        CP_COMMIT();
    }

    for (int c = 0; c < NCH; c++) {
        CP_WAIT(LOOKAHEAD - 1);
        __syncthreads();

        if (c + LOOKAHEAD < NCH)
            k2_load_stage(dyn2 + ((c + LOOKAHEAD) % STAGES)*STAGEB, wsrc, psrc,
                          c + LOOKAHEAD, tid);
        CP_COMMIT();

        uint32_t swu = dyn_u + (uint32_t)((c % STAGES)*STAGEB);
        uint32_t spu = swu + WTILEB;
        char*    sw  = dyn2 + (c % STAGES)*STAGEB;

        #pragma unroll
        for (int ks = 0; ks < 4; ks++) {
            uint32_t xo = (uint32_t)(ks << 5);
            uint32_t a[4][4];
            uint32_t bq[8][2];
            #pragma unroll
            for (int mg = 0; mg < 4; mg++)
                ldmx4(a[mg], swu + (offA[mg] ^ xo));
            #pragma unroll
            for (int h = 0; h < 4; h++) {
                uint32_t r[4];
                ldmx4(r, spu + (offB[h] ^ xo));
                bq[h*2][0]   = r[0]; bq[h*2][1]   = r[1];
                bq[h*2+1][0] = r[2]; bq[h*2+1][1] = r[3];
            }
            #pragma unroll
            for (int t = 0; t < 4; t++)
                #pragma unroll
                for (int ot = 0; ot < 8; ot++)
                    mma_tf32(acc[t][ot], a[t], bq[ot]);
        }

        // fused W copy-out
        #pragma unroll
        for (int i = 0; i < 8; i++) {
            int q = i*THR2 + tid;
            int row = q >> 3, seg = q & 7;
            float4 v = *(const float4*)(sw + segoff(row, seg));
            *(float4*)(wdst + (size_t)row*KDIM + c*CHUNK + seg*4) = v;
        }
    }

    // epilogue: bias + relu -> g_z[b, o, mt*128 + m]
    #pragma unroll
    for (int t = 0; t < 4; t++) {
        int m0 = wy*64 + t*16 + g;
        #pragma unroll
        for (int ot = 0; ot < 8; ot++) {
            int o0 = wx*64 + ot*8 + 2*tig;
            float* z0 = g_z + ((size_t)(b*CH + o0))*NND + mt*MT;
            float* z1 = z0 + NND;   // o0+1
            float b0 = s_bias[o0], b1 = s_bias[o0+1];
            z0[m0]     = fmaxf(acc[t][ot][0] + b0, 0.0f);
            z1[m0]     = fmaxf(acc[t][ot][1] + b1, 0.0f);
            z0[m0 + 8] = fmaxf(acc[t][ot][2] + b0, 0.0f);
            z1[m0 + 8] = fmaxf(acc[t][ot][3] + b1, 0.0f);
        }
    }
}

// ---------------- K2b: per-channel masked sums ----------------
__global__ void __launch_bounds__(256, 4)
k2b_stats(const float* __restrict__ mask) {
    int row = blockIdx.x;           // b*128 + o
    int o = row & 127, b = row >> 7;
    const float* z = g_z + (size_t)row*NND;
    const float* mrow = mask + (size_t)b*NND;
    int tid = threadIdx.x;
    float s1 = 0.0f, s2 = 0.0f;
    for (int i = tid; i < NND/4; i += 256) {
        float4 v  = *(const float4*)(z + i*4);
        float4 mk = __ldg((const float4*)(mrow + i*4));
        s1 += v.x*mk.x + v.y*mk.y + v.z*mk.z + v.w*mk.w;
        s2 += v.x*v.x*mk.x + v.y*v.y*mk.y + v.z*v.z*mk.z + v.w*v.w*mk.w;
    }
    #pragma unroll
    for (int d = 16; d > 0; d >>= 1) {
        s1 += __shfl_xor_sync(0xFFFFFFFFu, s1, d);
        s2 += __shfl_xor_sync(0xFFFFFFFFu, s2, d);
    }
    __shared__ float r1[8], r2[8];
    if ((tid & 31) == 0) { r1[tid >> 5] = s1; r2[tid >> 5] = s2; }
    __syncthreads();
    if (tid == 0) {
        float t1 = 0.0f, t2 = 0.0f;
        #pragma unroll
        for (int i = 0; i < 8; i++) { t1 += r1[i]; t2 += r2[i]; }
        atomicAdd(&g_S1[o], t1);
        atomicAdd(&g_S2[o], t2);
    }
}

// ---------------- K2c: finalize scale/shift ----------------
__global__ void k2c_finstats(const float* __restrict__ gamma, const float* __restrict__ beta) {
    int o = threadIdx.x;
    if (o >= CH) return;
    float total = g_misc[0], M0 = g_misc[1];
    float s1 = g_S1[o], s2 = g_S2[o];
    float mean = s1 / total;
    float var = (s2 - 2.0f*mean*s1 + mean*mean*M0) / total;
    float sc = gamma[o] * rsqrtf(var + 1e-5f);
    g_scale[o] = sc;
    g_shift[o] = beta[o] - mean*sc;
}

// ---------------- K3: apply BN affine + mask -> out ----------------
__global__ void __launch_bounds__(256, 8)
k3_apply(const float* __restrict__ mask, float* __restrict__ out) {
    int idx4 = blockIdx.x*256 + threadIdx.x;   // float4 index
    int row = idx4 >> 9;                       // b*128 + o
    int o = row & 127, b = row >> 7;
    int m4 = idx4 & 511;
    float4 z  = *(const float4*)(g_z + (size_t)row*NND + m4*4);
    float4 mk = __ldg((const float4*)(mask + (size_t)b*NND + m4*4));
    float sc = g_scale[o], sh = g_shift[o];
    float4 r;
    r.x = (z.x*sc + sh)*mk.x;
    r.y = (z.y*sc + sh)*mk.y;
    r.z = (z.z*sc + sh)*mk.z;
    r.w = (z.w*sc + sh)*mk.w;
    *(float4*)(out + (size_t)row*NND + m4*4) = r;
}

// ---------------- launch ----------------
extern "C" void kernel_launch(void* const* d_in, const int* in_sizes, int n_in,
                              void* d_out, int out_size) {
    (void)in_sizes; (void)n_in; (void)out_size;
    const float* X     = (const float*)d_in[0];
    const float* W     = (const float*)d_in[1];
    const float* Nb    = (const float*)d_in[2];
    const float* mask  = (const float*)d_in[3];
    const float* cv1_w = (const float*)d_in[4];
    const float* cv1_b = (const float*)d_in[5];
    const float* cv2_w = (const float*)d_in[6];
    const float* cv2_b = (const float*)d_in[7];
    const float* gamma = (const float*)d_in[8];
    const float* beta  = (const float*)d_in[9];
    float* out  = (float*)d_out;
    float* outW = out + ZN;

    cudaFuncSetAttribute(k1_gemm, cudaFuncAttributeMaxDynamicSharedMemorySize, DYN1);
    cudaFuncSetAttribute(k2_gemm, cudaFuncAttributeMaxDynamicSharedMemorySize, DYN2);

    k0_init<<<1, 256>>>(Nb, mask);                               // launch 0
    k1_gemm<<<dim3(32, 8), 256, DYN1>>>(X, cv1_w, cv2_w);        // launch 1
    k_nop<<<1, 32>>>();                                          // launch 2 (slot shim)
    k2_gemm<<<dim3(16, 8), THR2, DYN2>>>(W, cv1_b, cv2_b, outW); // launch 3 <- ncu slot
    k2b_stats<<<BS*CH, 256>>>(mask);
    k2c_finstats<<<1, 128>>>(gamma, beta);
    k3_apply<<<ZN/4/256, 256>>>(mask, out);
}